// round 2
// baseline (speedup 1.0000x reference)
#include <cuda_runtime.h>
#include <cstdint>

// ---------------------------------------------------------------------------
// LoRALinear: out = x @ W^T + bias + (alpha/r) * (x @ A^T) @ B^T
// Shapes: x[4,4096,4096] -> M=16384, W[4096,4096], bias[4096],
//         lora_A[16,4096], lora_B[4096,16].  alpha/r = 16/16 = 1.
// Strategy: fold W_eff = rn_tf32(W + scale * B@A) once per launch (cheap),
//           then a single TF32 tensor-core GEMM with fused bias epilogue.
// ---------------------------------------------------------------------------

constexpr int M_TOT = 16384;
constexpr int N_TOT = 4096;
constexpr int K_TOT = 4096;
constexpr int RANK  = 16;
constexpr float LSCALE = 1.0f;   // alpha / max(1, r) = 16/16

// Scratch: folded weights (tf32-rounded). __device__ global (no runtime alloc).
__device__ float g_weff[(size_t)N_TOT * (size_t)K_TOT];

// ---------------- helpers ----------------
__device__ __forceinline__ uint32_t smem_u32(const void* p) {
    return (uint32_t)__cvta_generic_to_shared(p);
}

__device__ __forceinline__ float rn_tf32(float f) {
    uint32_t u;
    asm("cvt.rna.tf32.f32 %0, %1;" : "=r"(u) : "f"(f));
    return __uint_as_float(u);
}

__device__ __forceinline__ uint32_t rn_tf32_bits(uint32_t bits) {
    uint32_t u;
    asm("cvt.rna.tf32.f32 %0, %1;" : "=r"(u) : "f"(__uint_as_float(bits)));
    return u;
}

__device__ __forceinline__ void cp_async16(uint32_t s, const void* g) {
    asm volatile("cp.async.cg.shared.global [%0], [%1], 16;" :: "r"(s), "l"(g) : "memory");
}
__device__ __forceinline__ void cp_commit() {
    asm volatile("cp.async.commit_group;" ::: "memory");
}
__device__ __forceinline__ void cp_wait0() {
    asm volatile("cp.async.wait_group 0;" ::: "memory");
}

// ---------------- kernel 1: fold LoRA into weights ----------------
// g_weff[o][i] = rn_tf32( W[o][i] + LSCALE * sum_r lB[o][r] * lA[r][i] )
__global__ void fold_kernel(const float* __restrict__ W,
                            const float* __restrict__ lA,
                            const float* __restrict__ lB) {
    int total4 = N_TOT * K_TOT / 4;
    for (int idx = blockIdx.x * blockDim.x + threadIdx.x; idx < total4;
         idx += gridDim.x * blockDim.x) {
        int o  = idx / (K_TOT / 4);
        int i4 = idx % (K_TOT / 4);
        float4 w = reinterpret_cast<const float4*>(W)[idx];
        #pragma unroll
        for (int r = 0; r < RANK; r++) {
            float  b = __ldg(&lB[o * RANK + r]) * LSCALE;
            float4 a = reinterpret_cast<const float4*>(lA)[r * (K_TOT / 4) + i4];
            w.x += b * a.x; w.y += b * a.y; w.z += b * a.z; w.w += b * a.w;
        }
        w.x = rn_tf32(w.x); w.y = rn_tf32(w.y);
        w.z = rn_tf32(w.z); w.w = rn_tf32(w.w);
        reinterpret_cast<float4*>(g_weff)[idx] = w;
    }
}

// ---------------- kernel 2: TF32 GEMM, out = x @ Weff^T + bias ----------------
constexpr int BM = 128, BN = 128, BK = 32;
constexpr int LDSA = BK + 4;                 // 36 floats/row: conflict-free ldmatrix
constexpr int THREADS = 256;
constexpr int A_STAGE_F = BM * LDSA;         // floats per A stage
constexpr int B_STAGE_F = BN * LDSA;
constexpr int SMEM_BYTES = (2 * A_STAGE_F + 2 * B_STAGE_F) * 4;   // 73728

__device__ __forceinline__ void load_tiles(const float* __restrict__ X,
                                           const float* __restrict__ Wf,
                                           float* sm, int stage,
                                           int m0, int n0, int kt, int tid) {
    float* As = sm + stage * A_STAGE_F;
    float* Bs = sm + 2 * A_STAGE_F + stage * B_STAGE_F;
    int k0 = kt * BK;
    #pragma unroll
    for (int s = 0; s < 4; s++) {
        int c = tid + s * THREADS;           // 1024 16B-chunks per tile
        int row = c >> 3;
        int col = (c & 7) << 2;
        cp_async16(smem_u32(&As[row * LDSA + col]),
                   &X[(size_t)(m0 + row) * K_TOT + k0 + col]);
    }
    #pragma unroll
    for (int s = 0; s < 4; s++) {
        int c = tid + s * THREADS;
        int row = c >> 3;
        int col = (c & 7) << 2;
        cp_async16(smem_u32(&Bs[row * LDSA + col]),
                   &Wf[(size_t)(n0 + row) * K_TOT + k0 + col]);
    }
}

__global__ __launch_bounds__(THREADS, 2)
void gemm_kernel(const float* __restrict__ X,
                 const float* __restrict__ bias,
                 float* __restrict__ Out) {
    extern __shared__ float sm[];
    const float* Wf = g_weff;

    const int tid  = threadIdx.x;
    const int lane = tid & 31;
    const int warp = tid >> 5;
    const int wm = (warp >> 2) * 64;     // warp row offset in tile (0 or 64)
    const int wn = (warp & 3) * 32;      // warp col offset (0..96)

    const int m0 = blockIdx.x * BM;
    const int n0 = blockIdx.y * BN;

    // ldmatrix per-lane source offsets (in floats, within a stage)
    // A: 16x8 tf32 tile via m8n8.x4.b16: mats = [rows 0-7 k0-3][rows 8-15 k0-3]
    //                                           [rows 0-7 k4-7][rows 8-15 k4-7]
    const int agrp = lane >> 3;
    const int arow = wm + ((agrp & 1) << 3) + (lane & 7);
    const int acol = (agrp >> 1) << 2;
    const uint32_t a_off = (uint32_t)(arow * LDSA + acol) * 4u;
    // B: 8x8 tf32 tile via m8n8.x2.b16: mat0 = rows(n) 0-7 k0-3, mat1 = k4-7
    const int bl   = lane & 15;
    const int brow = wn + (bl & 7);
    const int bcol = (bl >> 3) << 2;
    const uint32_t b_off = (uint32_t)(brow * LDSA + bcol) * 4u;

    const uint32_t smem_base = smem_u32(sm);
    const uint32_t a_stage_b = (uint32_t)A_STAGE_F * 4u;
    const uint32_t b_base0   = smem_base + 2u * a_stage_b;
    const uint32_t b_stage_b = (uint32_t)B_STAGE_F * 4u;

    float acc[4][4][4];
    #pragma unroll
    for (int i = 0; i < 4; i++)
        #pragma unroll
        for (int j = 0; j < 4; j++)
            #pragma unroll
            for (int q = 0; q < 4; q++) acc[i][j][q] = 0.f;

    const int KT = K_TOT / BK;   // 128
    load_tiles(X, Wf, sm, 0, m0, n0, 0, tid);
    cp_commit();

    for (int kt = 0; kt < KT; kt++) {
        const int cur = kt & 1;
        cp_wait0();
        __syncthreads();
        if (kt + 1 < KT) {
            load_tiles(X, Wf, sm, cur ^ 1, m0, n0, kt + 1, tid);
            cp_commit();
        }

        const uint32_t abase = smem_base + (uint32_t)cur * a_stage_b + a_off;
        const uint32_t bbase = b_base0 + (uint32_t)cur * b_stage_b + b_off;

        #pragma unroll
        for (int ks = 0; ks < 4; ks++) {
            uint32_t a[4][4];
            #pragma unroll
            for (int i = 0; i < 4; i++) {
                uint32_t addr = abase + (uint32_t)(i * 16 * LDSA + ks * 8) * 4u;
                asm volatile(
                    "ldmatrix.sync.aligned.m8n8.x4.shared.b16 {%0,%1,%2,%3}, [%4];"
                    : "=r"(a[i][0]), "=r"(a[i][1]), "=r"(a[i][2]), "=r"(a[i][3])
                    : "r"(addr));
            }
            // round x fragments to tf32-nearest (avoids truncation bias)
            #pragma unroll
            for (int i = 0; i < 4; i++)
                #pragma unroll
                for (int q = 0; q < 4; q++) a[i][q] = rn_tf32_bits(a[i][q]);

            uint32_t b[4][2];
            #pragma unroll
            for (int j = 0; j < 4; j++) {
                uint32_t addr = bbase + (uint32_t)(j * 8 * LDSA + ks * 8) * 4u;
                asm volatile(
                    "ldmatrix.sync.aligned.m8n8.x2.shared.b16 {%0,%1}, [%2];"
                    : "=r"(b[j][0]), "=r"(b[j][1])
                    : "r"(addr));
            }

            #pragma unroll
            for (int i = 0; i < 4; i++)
                #pragma unroll
                for (int j = 0; j < 4; j++) {
                    asm volatile(
                        "mma.sync.aligned.m16n8k8.row.col.f32.tf32.tf32.f32 "
                        "{%0,%1,%2,%3}, {%4,%5,%6,%7}, {%8,%9}, {%0,%1,%2,%3};"
                        : "+f"(acc[i][j][0]), "+f"(acc[i][j][1]),
                          "+f"(acc[i][j][2]), "+f"(acc[i][j][3])
                        : "r"(a[i][0]), "r"(a[i][1]), "r"(a[i][2]), "r"(a[i][3]),
                          "r"(b[j][0]), "r"(b[j][1]));
                }
        }
        __syncthreads();
    }

    // Epilogue: += bias, write out
    const int row0 = m0 + wm + (lane >> 2);
    const int col0 = n0 + wn + ((lane & 3) << 1);
    #pragma unroll
    for (int i = 0; i < 4; i++) {
        #pragma unroll
        for (int j = 0; j < 4; j++) {
            int r = row0 + i * 16;
            int c = col0 + j * 8;
            float2 bv = *reinterpret_cast<const float2*>(&bias[c]);
            float2 v0 = make_float2(acc[i][j][0] + bv.x, acc[i][j][1] + bv.y);
            float2 v1 = make_float2(acc[i][j][2] + bv.x, acc[i][j][3] + bv.y);
            *reinterpret_cast<float2*>(&Out[(size_t)r * N_TOT + c])       = v0;
            *reinterpret_cast<float2*>(&Out[(size_t)(r + 8) * N_TOT + c]) = v1;
        }
    }
}

// ---------------- launch ----------------
extern "C" void kernel_launch(void* const* d_in, const int* in_sizes, int n_in,
                              void* d_out, int out_size) {
    const float* x    = (const float*)d_in[0];
    const float* W    = (const float*)d_in[1];
    const float* bias = (const float*)d_in[2];
    const float* lA   = (const float*)d_in[3];
    const float* lB   = (const float*)d_in[4];
    float* out = (float*)d_out;

    (void)in_sizes; (void)n_in; (void)out_size;

    fold_kernel<<<4096, 256>>>(W, lA, lB);

    cudaFuncSetAttribute(gemm_kernel,
                         cudaFuncAttributeMaxDynamicSharedMemorySize, SMEM_BYTES);
    dim3 grid(M_TOT / BM, N_TOT / BN);   // (128, 32)
    gemm_kernel<<<grid, THREADS, SMEM_BYTES>>>(x, bias, out);
}

// round 5
// speedup vs baseline: 2.2413x; 2.2413x over previous
#include <cuda_runtime.h>
#include <cuda_fp16.h>
#include <cstdint>

// ---------------------------------------------------------------------------
// LoRALinear (sm_103 base-target safe — NO tcgen05):
//   1) g_xh = fp16_rn(x)
//   2) g_wh = fp16_rn(W + (alpha/r) * B@A)
//   3) out  = g_xh @ g_wh^T + bias  via mma.sync.m16n8k16.f16 (fp32 accum)
// fp16 mantissa == tf32 mantissa (10 bits) -> same accuracy as the passing
// tf32 run (rel_err 2.4e-4) at 2x per-instruction tensor throughput.
// ---------------------------------------------------------------------------

constexpr int M_TOT = 16384;
constexpr int N_TOT = 4096;
constexpr int K_TOT = 4096;
constexpr int RANK  = 16;
constexpr float LSCALE = 1.0f;     // alpha / max(1,r) = 16/16

__device__ __half g_xh[(size_t)M_TOT * (size_t)K_TOT];
__device__ __half g_wh[(size_t)N_TOT * (size_t)K_TOT];

// ---------------- helpers ----------------
__device__ __forceinline__ uint32_t smem_u32(const void* p) {
    return (uint32_t)__cvta_generic_to_shared(p);
}
__device__ __forceinline__ void cp_async16(uint32_t s, const void* g) {
    asm volatile("cp.async.cg.shared.global [%0], [%1], 16;" :: "r"(s), "l"(g) : "memory");
}
__device__ __forceinline__ void cp_commit() {
    asm volatile("cp.async.commit_group;" ::: "memory");
}
template <int N> __device__ __forceinline__ void cp_wait() {
    asm volatile("cp.async.wait_group %0;" :: "n"(N) : "memory");
}

// ---------------- kernel 1: x -> fp16 ----------------
__global__ void conv_x_kernel(const float4* __restrict__ X) {
    size_t n4 = (size_t)M_TOT * K_TOT / 4;
    uint2* o = reinterpret_cast<uint2*>(g_xh);
    for (size_t i = (size_t)blockIdx.x * blockDim.x + threadIdx.x; i < n4;
         i += (size_t)gridDim.x * blockDim.x) {
        float4 v = X[i];
        __half2 h0 = __floats2half2_rn(v.x, v.y);
        __half2 h1 = __floats2half2_rn(v.z, v.w);
        o[i] = make_uint2(*reinterpret_cast<uint32_t*>(&h0),
                          *reinterpret_cast<uint32_t*>(&h1));
    }
}

// ---------------- kernel 2: fold LoRA into fp16 weights ----------------
__global__ void fold_kernel(const float* __restrict__ W,
                            const float* __restrict__ lA,
                            const float* __restrict__ lB) {
    int total4 = N_TOT * K_TOT / 4;
    uint2* out = reinterpret_cast<uint2*>(g_wh);
    for (int idx = blockIdx.x * blockDim.x + threadIdx.x; idx < total4;
         idx += gridDim.x * blockDim.x) {
        int o  = idx / (K_TOT / 4);
        int i4 = idx % (K_TOT / 4);
        float4 w = reinterpret_cast<const float4*>(W)[idx];
        #pragma unroll
        for (int r = 0; r < RANK; r++) {
            float  b = __ldg(&lB[o * RANK + r]) * LSCALE;
            float4 a = reinterpret_cast<const float4*>(lA)[r * (K_TOT / 4) + i4];
            w.x += b * a.x; w.y += b * a.y; w.z += b * a.z; w.w += b * a.w;
        }
        __half2 h0 = __floats2half2_rn(w.x, w.y);
        __half2 h1 = __floats2half2_rn(w.z, w.w);
        out[idx] = make_uint2(*reinterpret_cast<uint32_t*>(&h0),
                              *reinterpret_cast<uint32_t*>(&h1));
    }
}

// ---------------- kernel 3: fp16 tensor-core GEMM ----------------
constexpr int BM = 128, BN = 128, BK = 64;   // BK halfs = 128 B row
constexpr int STAGES = 3;
constexpr int A_BYTES   = BM * BK * 2;       // 16384
constexpr int B_BYTES   = BN * BK * 2;       // 16384
constexpr int STG_BYTES = A_BYTES + B_BYTES; // 32768
constexpr int SMEM_BYTES = STAGES * STG_BYTES;  // 98304
constexpr int KT = K_TOT / BK;               // 64
constexpr int THREADS = 256;

__device__ __forceinline__ uint32_t sw128(uint32_t off) {
    return off ^ ((off >> 3) & 0x70);
}

__device__ __forceinline__ void load_stage(uint32_t base, int q, int m0, int n0,
                                           int tid) {
    const uint32_t s = (uint32_t)q % 3u;
    const int k0 = q * BK;
    const uint32_t abase = base + s * STG_BYTES;
    const uint32_t bbase = abase + A_BYTES;
    #pragma unroll
    for (int i = 0; i < 4; i++) {            // A: 1024 x 16B
        int c = tid + i * THREADS;
        int row = c >> 3, kc = c & 7;
        cp_async16(abase + sw128((uint32_t)(row * 128 + kc * 16)),
                   &g_xh[(size_t)(m0 + row) * K_TOT + k0 + kc * 8]);
    }
    #pragma unroll
    for (int i = 0; i < 4; i++) {            // B: 1024 x 16B
        int c = tid + i * THREADS;
        int row = c >> 3, kc = c & 7;
        cp_async16(bbase + sw128((uint32_t)(row * 128 + kc * 16)),
                   &g_wh[(size_t)(n0 + row) * K_TOT + k0 + kc * 8]);
    }
}

__global__ __launch_bounds__(THREADS, 2)
void gemm_kernel(const float* __restrict__ bias, float* __restrict__ Out) {
    extern __shared__ char smraw[];
    const uint32_t base = smem_u32(smraw);

    const int tid  = threadIdx.x;
    const int lane = tid & 31;
    const int warp = tid >> 5;
    const int wm = (warp >> 2) * 64;         // 0 / 64
    const int wn = (warp & 3) * 32;          // 0..96
    const int m0 = blockIdx.x * BM;
    const int n0 = blockIdx.y * BN;

    // ldmatrix lane offsets (bytes within stage, pre-swizzle applied per use)
    const int a_row  = (lane & 15);
    const int a_koff = (lane >> 4) * 16;     // 0 or 16 bytes (k 0-7 / 8-15)
    const int b_row  = (lane & 7);
    const int b_koff = ((lane >> 3) & 1) * 16;

    float acc[4][4][4];
    #pragma unroll
    for (int i = 0; i < 4; i++)
        #pragma unroll
        for (int j = 0; j < 4; j++)
            #pragma unroll
            for (int q = 0; q < 4; q++) acc[i][j][q] = 0.f;

    load_stage(base, 0, m0, n0, tid); cp_commit();
    load_stage(base, 1, m0, n0, tid); cp_commit();

    uint32_t cur = 0;                        // stage index of tile kt
    for (int kt = 0; kt < KT; kt++) {
        if (kt + 2 < KT) { load_stage(base, kt + 2, m0, n0, tid); cp_commit(); }
        if (kt + 2 < KT)      cp_wait<2>();
        else if (kt + 1 < KT) cp_wait<1>();
        else                  cp_wait<0>();
        __syncthreads();

        const uint32_t abase = base + cur * STG_BYTES;
        const uint32_t bbase = abase + A_BYTES;

        #pragma unroll
        for (int ks = 0; ks < 4; ks++) {     // 4 x k16 per stage
            uint32_t a[4][4];
            #pragma unroll
            for (int i = 0; i < 4; i++) {
                uint32_t off = (uint32_t)((wm + i * 16 + a_row) * 128 +
                                          ks * 32 + a_koff);
                uint32_t addr = abase + sw128(off);
                asm volatile(
                    "ldmatrix.sync.aligned.m8n8.x4.shared.b16 {%0,%1,%2,%3}, [%4];"
                    : "=r"(a[i][0]), "=r"(a[i][1]), "=r"(a[i][2]), "=r"(a[i][3])
                    : "r"(addr));
            }
            uint32_t b[4][2];
            #pragma unroll
            for (int j = 0; j < 4; j++) {
                uint32_t off = (uint32_t)((wn + j * 8 + b_row) * 128 +
                                          ks * 32 + b_koff);
                uint32_t addr = bbase + sw128(off);
                asm volatile(
                    "ldmatrix.sync.aligned.m8n8.x2.shared.b16 {%0,%1}, [%2];"
                    : "=r"(b[j][0]), "=r"(b[j][1])
                    : "r"(addr));
            }
            #pragma unroll
            for (int i = 0; i < 4; i++)
                #pragma unroll
                for (int j = 0; j < 4; j++) {
                    asm volatile(
                        "mma.sync.aligned.m16n8k16.row.col.f32.f16.f16.f32 "
                        "{%0,%1,%2,%3}, {%4,%5,%6,%7}, {%8,%9}, {%0,%1,%2,%3};"
                        : "+f"(acc[i][j][0]), "+f"(acc[i][j][1]),
                          "+f"(acc[i][j][2]), "+f"(acc[i][j][3])
                        : "r"(a[i][0]), "r"(a[i][1]), "r"(a[i][2]), "r"(a[i][3]),
                          "r"(b[j][0]), "r"(b[j][1]));
                }
        }
        __syncthreads();
        cur = (cur == 2) ? 0 : cur + 1;
    }

    // Epilogue: += bias, write out
    const int row0 = m0 + wm + (lane >> 2);
    const int col0 = n0 + wn + ((lane & 3) << 1);
    #pragma unroll
    for (int i = 0; i < 4; i++) {
        #pragma unroll
        for (int j = 0; j < 4; j++) {
            int r = row0 + i * 16;
            int c = col0 + j * 8;
            float2 bv = *reinterpret_cast<const float2*>(&bias[c]);
            float2 v0 = make_float2(acc[i][j][0] + bv.x, acc[i][j][1] + bv.y);
            float2 v1 = make_float2(acc[i][j][2] + bv.x, acc[i][j][3] + bv.y);
            *reinterpret_cast<float2*>(&Out[(size_t)r * N_TOT + c])       = v0;
            *reinterpret_cast<float2*>(&Out[(size_t)(r + 8) * N_TOT + c]) = v1;
        }
    }
}

// ---------------- launch ----------------
extern "C" void kernel_launch(void* const* d_in, const int* in_sizes, int n_in,
                              void* d_out, int out_size) {
    const float* x    = (const float*)d_in[0];
    const float* W    = (const float*)d_in[1];
    const float* bias = (const float*)d_in[2];
    const float* lA   = (const float*)d_in[3];
    const float* lB   = (const float*)d_in[4];
    float* out = (float*)d_out;
    (void)in_sizes; (void)n_in; (void)out_size;

    conv_x_kernel<<<8192, 256>>>(reinterpret_cast<const float4*>(x));
    fold_kernel<<<4096, 256>>>(W, lA, lB);

    cudaFuncSetAttribute(gemm_kernel,
                         cudaFuncAttributeMaxDynamicSharedMemorySize, SMEM_BYTES);
    dim3 grid(M_TOT / BM, N_TOT / BN);       // (128, 32)
    gemm_kernel<<<grid, THREADS, SMEM_BYTES>>>(bias, out);
}

// round 6
// speedup vs baseline: 2.5201x; 1.1244x over previous
#include <cuda_runtime.h>
#include <cuda_fp16.h>
#include <cstdint>

// ---------------------------------------------------------------------------
// LoRALinear (sm_103 base-target safe — NO tcgen05):
//   1) g_xh = fp16_rn(x)
//   2) g_wh = fp16_rn(W + (alpha/r) * B@A)
//   3) out  = g_xh @ g_wh^T + bias  via mma.sync.m16n8k16.f16 (fp32 accum)
// Single-__syncthreads multistage mainloop, x4 ldmatrix for both operands.
// ---------------------------------------------------------------------------

constexpr int M_TOT = 16384;
constexpr int N_TOT = 4096;
constexpr int K_TOT = 4096;
constexpr int RANK  = 16;
constexpr float LSCALE = 1.0f;     // alpha / max(1,r) = 16/16

__device__ __half g_xh[(size_t)M_TOT * (size_t)K_TOT];
__device__ __half g_wh[(size_t)N_TOT * (size_t)K_TOT];

// ---------------- helpers ----------------
__device__ __forceinline__ uint32_t smem_u32(const void* p) {
    return (uint32_t)__cvta_generic_to_shared(p);
}
__device__ __forceinline__ void cp_async16(uint32_t s, const void* g) {
    asm volatile("cp.async.cg.shared.global [%0], [%1], 16;" :: "r"(s), "l"(g) : "memory");
}
__device__ __forceinline__ void cp_commit() {
    asm volatile("cp.async.commit_group;" ::: "memory");
}
template <int N> __device__ __forceinline__ void cp_wait() {
    asm volatile("cp.async.wait_group %0;" :: "n"(N) : "memory");
}

// ---------------- kernel 1: x -> fp16 ----------------
__global__ void conv_x_kernel(const float4* __restrict__ X) {
    size_t n4 = (size_t)M_TOT * K_TOT / 4;
    uint2* o = reinterpret_cast<uint2*>(g_xh);
    for (size_t i = (size_t)blockIdx.x * blockDim.x + threadIdx.x; i < n4;
         i += (size_t)gridDim.x * blockDim.x) {
        float4 v = X[i];
        __half2 h0 = __floats2half2_rn(v.x, v.y);
        __half2 h1 = __floats2half2_rn(v.z, v.w);
        o[i] = make_uint2(*reinterpret_cast<uint32_t*>(&h0),
                          *reinterpret_cast<uint32_t*>(&h1));
    }
}

// ---------------- kernel 2: fold LoRA into fp16 weights ----------------
__global__ void fold_kernel(const float* __restrict__ W,
                            const float* __restrict__ lA,
                            const float* __restrict__ lB) {
    int total4 = N_TOT * K_TOT / 4;
    uint2* out = reinterpret_cast<uint2*>(g_wh);
    for (int idx = blockIdx.x * blockDim.x + threadIdx.x; idx < total4;
         idx += gridDim.x * blockDim.x) {
        int o  = idx / (K_TOT / 4);
        int i4 = idx % (K_TOT / 4);
        float4 w = reinterpret_cast<const float4*>(W)[idx];
        #pragma unroll
        for (int r = 0; r < RANK; r++) {
            float  b = __ldg(&lB[o * RANK + r]) * LSCALE;
            float4 a = reinterpret_cast<const float4*>(lA)[r * (K_TOT / 4) + i4];
            w.x += b * a.x; w.y += b * a.y; w.z += b * a.z; w.w += b * a.w;
        }
        __half2 h0 = __floats2half2_rn(w.x, w.y);
        __half2 h1 = __floats2half2_rn(w.z, w.w);
        out[idx] = make_uint2(*reinterpret_cast<uint32_t*>(&h0),
                              *reinterpret_cast<uint32_t*>(&h1));
    }
}

// ---------------- kernel 3: fp16 tensor-core GEMM ----------------
constexpr int BM = 128, BN = 128, BK = 64;   // BK halfs = 128 B row
constexpr int A_BYTES   = BM * BK * 2;       // 16384
constexpr int B_BYTES   = BN * BK * 2;       // 16384
constexpr int STG_BYTES = A_BYTES + B_BYTES; // 32768
constexpr int SMEM_BYTES = 3 * STG_BYTES;    // 98304
constexpr int KT = K_TOT / BK;               // 64
constexpr int THREADS = 256;

__device__ __forceinline__ uint32_t sw128(uint32_t off) {
    return off ^ ((off >> 3) & 0x70);
}

__device__ __forceinline__ void load_stage(uint32_t base, int q, int m0, int n0,
                                           int tid) {
    const uint32_t s = (uint32_t)q % 3u;
    const int k0 = q * BK;
    const uint32_t abase = base + s * STG_BYTES;
    const uint32_t bbase = abase + A_BYTES;
    #pragma unroll
    for (int i = 0; i < 4; i++) {            // A: 1024 x 16B
        int c = tid + i * THREADS;
        int row = c >> 3, kc = c & 7;
        cp_async16(abase + sw128((uint32_t)(row * 128 + kc * 16)),
                   &g_xh[(size_t)(m0 + row) * K_TOT + k0 + kc * 8]);
    }
    #pragma unroll
    for (int i = 0; i < 4; i++) {            // B: 1024 x 16B
        int c = tid + i * THREADS;
        int row = c >> 3, kc = c & 7;
        cp_async16(bbase + sw128((uint32_t)(row * 128 + kc * 16)),
                   &g_wh[(size_t)(n0 + row) * K_TOT + k0 + kc * 8]);
    }
}

__global__ __launch_bounds__(THREADS, 2)
void gemm_kernel(const float* __restrict__ bias, float* __restrict__ Out) {
    extern __shared__ char smraw[];
    const uint32_t base = smem_u32(smraw);

    const int tid  = threadIdx.x;
    const int lane = tid & 31;
    const int warp = tid >> 5;
    const int wm = (warp >> 2) * 64;         // 0 / 64
    const int wn = (warp & 3) * 32;          // 0..96
    const int m0 = blockIdx.x * BM;
    const int n0 = blockIdx.y * BN;

    // ldmatrix lane source layout (pre-swizzle byte offsets within stage)
    // A x4: lanes 0-7 rows 0-7 k0-7 | 8-15 rows 8-15 k0-7 | 16-23 rows 0-7 k8-15 | 24-31 rows 8-15 k8-15
    const int a_row  = (lane & 15);
    const int a_koff = (lane >> 4) * 16;
    // B x4: lanes 0-7 n0-7 k0-7 | 8-15 n0-7 k8-15 | 16-23 n8-15 k0-7 | 24-31 n8-15 k8-15
    const int b_row  = ((lane >> 4) << 3) + (lane & 7);
    const int b_koff = ((lane >> 3) & 1) * 16;

    float acc[4][4][4];
    #pragma unroll
    for (int i = 0; i < 4; i++)
        #pragma unroll
        for (int j = 0; j < 4; j++)
            #pragma unroll
            for (int q = 0; q < 4; q++) acc[i][j][q] = 0.f;

    load_stage(base, 0, m0, n0, tid); cp_commit();
    load_stage(base, 1, m0, n0, tid); cp_commit();

    uint32_t cur = 0;                        // stage index of tile kt
    for (int kt = 0; kt < KT; kt++) {
        if (kt + 1 < KT) cp_wait<1>();       // stage kt resident
        else             cp_wait<0>();
        __syncthreads();                     // also fences stage-(kt+2)%3 reuse

        const uint32_t abase = base + cur * STG_BYTES;
        const uint32_t bbase = abase + A_BYTES;

        #pragma unroll
        for (int ks = 0; ks < 4; ks++) {     // 4 x k16 per stage
            uint32_t a[4][4];
            #pragma unroll
            for (int i = 0; i < 4; i++) {
                uint32_t off = (uint32_t)((wm + i * 16 + a_row) * 128 +
                                          ks * 32 + a_koff);
                uint32_t addr = abase + sw128(off);
                asm volatile(
                    "ldmatrix.sync.aligned.m8n8.x4.shared.b16 {%0,%1,%2,%3}, [%4];"
                    : "=r"(a[i][0]), "=r"(a[i][1]), "=r"(a[i][2]), "=r"(a[i][3])
                    : "r"(addr));
            }
            uint32_t b[2][4];                // b[j2] covers n-tiles 2*j2, 2*j2+1
            #pragma unroll
            for (int j2 = 0; j2 < 2; j2++) {
                uint32_t off = (uint32_t)((wn + j2 * 16 + b_row) * 128 +
                                          ks * 32 + b_koff);
                uint32_t addr = bbase + sw128(off);
                asm volatile(
                    "ldmatrix.sync.aligned.m8n8.x4.shared.b16 {%0,%1,%2,%3}, [%4];"
                    : "=r"(b[j2][0]), "=r"(b[j2][1]), "=r"(b[j2][2]), "=r"(b[j2][3])
                    : "r"(addr));
            }
            #pragma unroll
            for (int i = 0; i < 4; i++)
                #pragma unroll
                for (int j = 0; j < 4; j++) {
                    asm volatile(
                        "mma.sync.aligned.m16n8k16.row.col.f32.f16.f16.f32 "
                        "{%0,%1,%2,%3}, {%4,%5,%6,%7}, {%8,%9}, {%0,%1,%2,%3};"
                        : "+f"(acc[i][j][0]), "+f"(acc[i][j][1]),
                          "+f"(acc[i][j][2]), "+f"(acc[i][j][3])
                        : "r"(a[i][0]), "r"(a[i][1]), "r"(a[i][2]), "r"(a[i][3]),
                          "r"(b[j >> 1][(j & 1) * 2]), "r"(b[j >> 1][(j & 1) * 2 + 1]));
                }
            if (ks == 0 && kt + 2 < KT) {    // overlap next-stage loads w/ MMAs
                load_stage(base, kt + 2, m0, n0, tid);
                cp_commit();
            }
        }
        cur = (cur == 2) ? 0 : cur + 1;
    }

    // Epilogue: += bias, write out
    const int row0 = m0 + wm + (lane >> 2);
    const int col0 = n0 + wn + ((lane & 3) << 1);
    float2 bv[4];
    #pragma unroll
    for (int j = 0; j < 4; j++)
        bv[j] = *reinterpret_cast<const float2*>(&bias[col0 + j * 8]);
    #pragma unroll
    for (int i = 0; i < 4; i++) {
        #pragma unroll
        for (int j = 0; j < 4; j++) {
            int r = row0 + i * 16;
            int c = col0 + j * 8;
            float2 v0 = make_float2(acc[i][j][0] + bv[j].x, acc[i][j][1] + bv[j].y);
            float2 v1 = make_float2(acc[i][j][2] + bv[j].x, acc[i][j][3] + bv[j].y);
            *reinterpret_cast<float2*>(&Out[(size_t)r * N_TOT + c])       = v0;
            *reinterpret_cast<float2*>(&Out[(size_t)(r + 8) * N_TOT + c]) = v1;
        }
    }
}

// ---------------- launch ----------------
extern "C" void kernel_launch(void* const* d_in, const int* in_sizes, int n_in,
                              void* d_out, int out_size) {
    const float* x    = (const float*)d_in[0];
    const float* W    = (const float*)d_in[1];
    const float* bias = (const float*)d_in[2];
    const float* lA   = (const float*)d_in[3];
    const float* lB   = (const float*)d_in[4];
    float* out = (float*)d_out;
    (void)in_sizes; (void)n_in; (void)out_size;

    conv_x_kernel<<<8192, 256>>>(reinterpret_cast<const float4*>(x));
    fold_kernel<<<4096, 256>>>(W, lA, lB);

    cudaFuncSetAttribute(gemm_kernel,
                         cudaFuncAttributeMaxDynamicSharedMemorySize, SMEM_BYTES);
    dim3 grid(M_TOT / BM, N_TOT / BN);       // (128, 32)
    gemm_kernel<<<grid, THREADS, SMEM_BYTES>>>(bias, out);
}